// round 2
// baseline (speedup 1.0000x reference)
#include <cuda_runtime.h>
#include <math.h>

// Problem constants
#define NB 32768   // batch
#define TT 9       // time steps (T-1)
#define DD 81      // input dim
#define HH 128     // hidden
#define NG 512     // 4*HH gates

// rnn tiling
#define BM 64          // batch rows per block
#define WS_STRIDE 132  // weight tile row stride (floats), 16B-aligned rows
#define HS_STRIDE 130  // h/c/tmp row stride (floats): 8*130 % 32 != 0 -> no 2-way a-load conflict
#define AS_STRIDE 82   // w_in tile row stride

// device scratch (allowed: __device__ globals)
__device__ float g_Wtih[DD * NG];   // [k][r] = W_ih[r][k]
__device__ float g_Wthh[HH * NG];   // [k][r] = W_hh[r][k]
__device__ float g_bias[NG];        // b_ih + b_hh

// ---------------------------------------------------------------------------
// prep: transpose weights to k-major, fuse biases
// ---------------------------------------------------------------------------
__global__ void prep_kernel(const float* __restrict__ W_ih,
                            const float* __restrict__ W_hh,
                            const float* __restrict__ b_ih,
                            const float* __restrict__ b_hh) {
    int idx = blockIdx.x * blockDim.x + threadIdx.x;
    if (idx < DD * NG) {
        int k = idx / NG;
        int r = idx - k * NG;
        g_Wtih[idx] = W_ih[r * DD + k];
    } else if (idx < DD * NG + HH * NG) {
        int j = idx - DD * NG;
        int k = j / NG;
        int r = j - k * NG;
        g_Wthh[j] = W_hh[r * HH + k];
    } else if (idx < DD * NG + HH * NG + NG) {
        int r = idx - (DD * NG + HH * NG);
        g_bias[r] = b_ih[r] + b_hh[r];
    }
}

// ---------------------------------------------------------------------------
// attention: softmax over d of (sum_t x[b,t,d]*Wx[t]); write input_weighted.
// One warp per batch row. (softmax is invariant to the h/c scalar term.)
// ---------------------------------------------------------------------------
__global__ void attn_kernel(const float* __restrict__ x,
                            const float* __restrict__ W_attn,
                            float* __restrict__ out_w) {
    int gw = (blockIdx.x * blockDim.x + threadIdx.x) >> 5;
    int lane = threadIdx.x & 31;
    if (gw >= NB) return;

    float wx[TT];
#pragma unroll
    for (int tt = 0; tt < TT; tt++) wx[tt] = W_attn[2 * HH + tt];

    const float* xb = x + (size_t)gw * TT * DD;
    float xr[3][TT];
    float pre[3];
#pragma unroll
    for (int ii = 0; ii < 3; ii++) {
        int d = lane + 32 * ii;
        float p = 0.f;
#pragma unroll
        for (int tt = 0; tt < TT; tt++) {
            float v = (d < DD) ? xb[tt * DD + d] : 0.f;
            xr[ii][tt] = v;
            p = fmaf(v, wx[tt], p);
        }
        pre[ii] = (d < DD) ? p : -3.0e38f;
    }
    float mx = fmaxf(pre[0], fmaxf(pre[1], pre[2]));
#pragma unroll
    for (int o = 16; o > 0; o >>= 1) mx = fmaxf(mx, __shfl_xor_sync(0xffffffffu, mx, o));

    float ev[3];
    float s = 0.f;
#pragma unroll
    for (int ii = 0; ii < 3; ii++) {
        int d = lane + 32 * ii;
        ev[ii] = (d < DD) ? __expf(pre[ii] - mx) : 0.f;
        s += ev[ii];
    }
#pragma unroll
    for (int o = 16; o > 0; o >>= 1) s += __shfl_xor_sync(0xffffffffu, s, o);
    float inv = 1.f / s;

    float* ob = out_w + (size_t)gw * TT * DD;
#pragma unroll
    for (int ii = 0; ii < 3; ii++) {
        int d = lane + 32 * ii;
        if (d < DD) {
            float a = ev[ii] * inv;
#pragma unroll
            for (int tt = 0; tt < TT; tt++) ob[tt * DD + d] = a * xr[ii][tt];
        }
    }
}

// ---------------------------------------------------------------------------
// recurrence: per block, 64 batch rows across all 9 steps. 128 threads,
// 8x8 register micro-tile. Gate chunks processed i -> g -> f -> o with
// incremental LSTM update (one temp buffer).
// ---------------------------------------------------------------------------
__device__ __forceinline__ float sigmoidf_(float v) {
    return 1.f / (1.f + __expf(-v));
}

__global__ __launch_bounds__(128, 1)
void rnn_kernel(const float* __restrict__ out_w, float* __restrict__ out_enc) {
    extern __shared__ float sm[];
    float* w_s    = sm;                          // 128 x 132
    float* h_s    = w_s + HH * WS_STRIDE;        // 64 x 130
    float* c_s    = h_s + BM * HS_STRIDE;        // 64 x 130
    float* tmp_s  = c_s + BM * HS_STRIDE;        // 64 x 130
    float* a_s    = tmp_s + BM * HS_STRIDE;      // 64 x 82
    float* bias_s = a_s + BM * AS_STRIDE;        // 512

    const int tid = threadIdx.x;
    const int tx = tid & 15;       // n dimension (column group)
    const int ty = tid >> 4;       // m dimension (row group, 0..7)
    const int b0 = blockIdx.x * BM;

    for (int i = tid; i < BM * HS_STRIDE; i += 128) { h_s[i] = 0.f; c_s[i] = 0.f; }
    for (int i = tid; i < NG; i += 128) bias_s[i] = g_bias[i];
    __syncthreads();

    for (int t = 0; t < TT; t++) {
        // stage w_in tile for this step
        for (int idx = tid; idx < BM * DD; idx += 128) {
            int m = idx / DD;
            int d = idx - m * DD;
            a_s[m * AS_STRIDE + d] = out_w[(((size_t)(b0 + m)) * TT + t) * DD + d];
        }
        __syncthreads();

#pragma unroll 1
        for (int cc = 0; cc < 4; cc++) {
            // chunk order i(0), g(2), f(1), o(3)
            const int q = (cc == 0) ? 0 : (cc == 1) ? 2 : (cc == 2) ? 1 : 3;

            float acc[8][8];
#pragma unroll
            for (int i = 0; i < 8; i++)
#pragma unroll
                for (int j = 0; j < 8; j++) acc[i][j] = 0.f;

            // stage ih weight chunk: w_s[k][n] = W_ih[q*128+n][k], k<81 (float4)
            for (int idx = tid; idx < DD * 32; idx += 128) {
                int k = idx >> 5;
                int n4 = idx & 31;
                *(float4*)(w_s + k * WS_STRIDE + n4 * 4) =
                    *(const float4*)(g_Wtih + k * NG + q * HH + n4 * 4);
            }
            __syncthreads();

            // GEMM over w_in (K = 81)
#pragma unroll 1
            for (int k = 0; k < DD; k++) {
                float a[8], b[8];
#pragma unroll
                for (int i = 0; i < 8; i++) a[i] = a_s[(ty * 8 + i) * AS_STRIDE + k];
#pragma unroll
                for (int j = 0; j < 8; j++) b[j] = w_s[k * WS_STRIDE + tx + 16 * j];
#pragma unroll
                for (int i = 0; i < 8; i++)
#pragma unroll
                    for (int j = 0; j < 8; j++) acc[i][j] = fmaf(a[i], b[j], acc[i][j]);
            }
            __syncthreads();

            // stage hh weight chunk: w_s[k][n] = W_hh[q*128+n][k], k<128
            for (int idx = tid; idx < HH * 32; idx += 128) {
                int k = idx >> 5;
                int n4 = idx & 31;
                *(float4*)(w_s + k * WS_STRIDE + n4 * 4) =
                    *(const float4*)(g_Wthh + k * NG + q * HH + n4 * 4);
            }
            __syncthreads();

            // GEMM over h (K = 128)
#pragma unroll 1
            for (int k = 0; k < HH; k++) {
                float a[8], b[8];
#pragma unroll
                for (int i = 0; i < 8; i++) a[i] = h_s[(ty * 8 + i) * HS_STRIDE + k];
#pragma unroll
                for (int j = 0; j < 8; j++) b[j] = w_s[k * WS_STRIDE + tx + 16 * j];
#pragma unroll
                for (int i = 0; i < 8; i++)
#pragma unroll
                    for (int j = 0; j < 8; j++) acc[i][j] = fmaf(a[i], b[j], acc[i][j]);
            }
            __syncthreads();

            // elementwise gate processing (each (m,n) owned by exactly one thread)
#pragma unroll
            for (int i = 0; i < 8; i++) {
                int m = ty * 8 + i;
#pragma unroll
                for (int j = 0; j < 8; j++) {
                    int n = tx + 16 * j;
                    float g = acc[i][j] + bias_s[q * HH + n];
                    int hidx = m * HS_STRIDE + n;
                    if (q == 0) {
                        tmp_s[hidx] = sigmoidf_(g);                 // sig(i)
                    } else if (q == 2) {
                        tmp_s[hidx] *= tanhf(g);                    // sig(i)*tanh(g)
                    } else if (q == 1) {
                        c_s[hidx] = sigmoidf_(g) * c_s[hidx] + tmp_s[hidx];  // new c
                    } else {
                        float h2 = sigmoidf_(g) * tanhf(c_s[hidx]);
                        h_s[hidx] = h2;
                        out_enc[(((size_t)(b0 + m)) * TT + t) * HH + n] = h2;
                    }
                }
            }
            __syncthreads();
        }
    }
}

// ---------------------------------------------------------------------------
// launch
// ---------------------------------------------------------------------------
extern "C" void kernel_launch(void* const* d_in, const int* in_sizes, int n_in,
                              void* d_out, int out_size) {
    const float* x      = (const float*)d_in[0];
    const float* W_attn = (const float*)d_in[1];
    // d_in[2] = b_attn: cancels in softmax, unused
    const float* W_ih   = (const float*)d_in[3];
    const float* W_hh   = (const float*)d_in[4];
    const float* b_ih   = (const float*)d_in[5];
    const float* b_hh   = (const float*)d_in[6];

    float* out    = (float*)d_out;
    float* out_w  = out;                               // (B, 9, 81)
    float* out_enc = out + (size_t)NB * TT * DD;       // (B, 9, 128)

    // prep: (81*512 + 128*512 + 512) = 107520 elements
    prep_kernel<<<420, 256>>>(W_ih, W_hh, b_ih, b_hh);

    // attention + input_weighted: 1 warp per row, 8 rows per block
    attn_kernel<<<NB / 8, 256>>>(x, W_attn, out_w);

    // recurrence
    const int smem_bytes =
        (HH * WS_STRIDE + 3 * BM * HS_STRIDE + BM * AS_STRIDE + NG) * (int)sizeof(float);
    cudaFuncSetAttribute(rnn_kernel, cudaFuncAttributeMaxDynamicSharedMemorySize, smem_bytes);
    rnn_kernel<<<NB / BM, 128, smem_bytes>>>(out_w, out_enc);
}

// round 3
// speedup vs baseline: 2.0592x; 2.0592x over previous
#include <cuda_runtime.h>
#include <math.h>

// Problem constants
#define NB 32768   // batch
#define TT 9       // time steps (T-1)
#define DD 81      // input dim
#define HH 128     // hidden
#define NG 512     // 4*HH gates

// rnn tiling
#define BM 64      // batch rows per block
#define WS 132     // weight tile row stride (floats)
#define HS 132     // h row stride (floats)
#define AS 84      // w_in tile row stride (floats), K padded 81->84

// device scratch
__device__ float g_Wtih[DD * NG];   // [k][r] = W_ih[r][k]
__device__ float g_Wthh[HH * NG];   // [k][r] = W_hh[r][k]
__device__ float g_bias[NG];        // b_ih + b_hh

// ---------------------------------------------------------------------------
__global__ void prep_kernel(const float* __restrict__ W_ih,
                            const float* __restrict__ W_hh,
                            const float* __restrict__ b_ih,
                            const float* __restrict__ b_hh) {
    int idx = blockIdx.x * blockDim.x + threadIdx.x;
    if (idx < DD * NG) {
        int k = idx / NG;
        int r = idx - k * NG;
        g_Wtih[idx] = W_ih[r * DD + k];
    } else if (idx < DD * NG + HH * NG) {
        int j = idx - DD * NG;
        int k = j / NG;
        int r = j - k * NG;
        g_Wthh[j] = W_hh[r * HH + k];
    } else if (idx < DD * NG + HH * NG + NG) {
        int r = idx - (DD * NG + HH * NG);
        g_bias[r] = b_ih[r] + b_hh[r];
    }
}

// ---------------------------------------------------------------------------
// attention: softmax over d of (sum_t x[b,t,d]*Wx[t]); write input_weighted.
// (softmax is invariant to the per-row h/c scalar and b_attn.)
// ---------------------------------------------------------------------------
__global__ void attn_kernel(const float* __restrict__ x,
                            const float* __restrict__ W_attn,
                            float* __restrict__ out_w) {
    int gw = (blockIdx.x * blockDim.x + threadIdx.x) >> 5;
    int lane = threadIdx.x & 31;
    if (gw >= NB) return;

    float wx[TT];
#pragma unroll
    for (int tt = 0; tt < TT; tt++) wx[tt] = W_attn[2 * HH + tt];

    const float* xb = x + (size_t)gw * TT * DD;
    float xr[3][TT];
    float pre[3];
#pragma unroll
    for (int ii = 0; ii < 3; ii++) {
        int d = lane + 32 * ii;
        float p = 0.f;
#pragma unroll
        for (int tt = 0; tt < TT; tt++) {
            float v = (d < DD) ? xb[tt * DD + d] : 0.f;
            xr[ii][tt] = v;
            p = fmaf(v, wx[tt], p);
        }
        pre[ii] = (d < DD) ? p : -3.0e38f;
    }
    float mx = fmaxf(pre[0], fmaxf(pre[1], pre[2]));
#pragma unroll
    for (int o = 16; o > 0; o >>= 1) mx = fmaxf(mx, __shfl_xor_sync(0xffffffffu, mx, o));

    float ev[3];
    float s = 0.f;
#pragma unroll
    for (int ii = 0; ii < 3; ii++) {
        int d = lane + 32 * ii;
        ev[ii] = (d < DD) ? __expf(pre[ii] - mx) : 0.f;
        s += ev[ii];
    }
#pragma unroll
    for (int o = 16; o > 0; o >>= 1) s += __shfl_xor_sync(0xffffffffu, s, o);
    float inv = 1.f / s;

    float* ob = out_w + (size_t)gw * TT * DD;
#pragma unroll
    for (int ii = 0; ii < 3; ii++) {
        int d = lane + 32 * ii;
        if (d < DD) {
            float a = ev[ii] * inv;
#pragma unroll
            for (int tt = 0; tt < TT; tt++) ob[tt * DD + d] = a * xr[ii][tt];
        }
    }
}

// ---------------------------------------------------------------------------
// f32x2 packed-FMA helpers
// ---------------------------------------------------------------------------
__device__ __forceinline__ unsigned long long pack_dup(float a) {
    unsigned long long r;
    asm("mov.b64 %0, {%1, %1};" : "=l"(r) : "f"(a));
    return r;
}
__device__ __forceinline__ void ffma2(unsigned long long& acc,
                                      unsigned long long a2,
                                      unsigned long long b2) {
    asm("fma.rn.f32x2 %0, %1, %2, %0;" : "+l"(acc) : "l"(a2), "l"(b2));
}
__device__ __forceinline__ void unpack2(unsigned long long v, float& lo, float& hi) {
    asm("mov.b64 {%0, %1}, %2;" : "=f"(lo), "=f"(hi) : "l"(v));
}
__device__ __forceinline__ float sigmoidf_(float v) {
    return __fdividef(1.f, 1.f + __expf(-v));
}
__device__ __forceinline__ float tanhf_(float v) {
    // tanh(x) = 2/(1+e^(-2x)) - 1
    return __fdividef(2.f, 1.f + __expf(-2.f * v)) - 1.f;
}

// ---------------------------------------------------------------------------
// recurrence: 256 threads, BM=64 batch rows per block, thread tile 8m x 4n.
// acc in f32x2 pairs; c and i*tanh(g) temp live in registers.
// ---------------------------------------------------------------------------
__global__ __launch_bounds__(256, 1)
void rnn_kernel(const float* __restrict__ out_w, float* __restrict__ out_enc) {
    extern __shared__ float sm[];
    float* w_s    = sm;                    // 128 x 132
    float* h_s    = w_s + HH * WS;         // 64 x 132
    float* a_s    = h_s + BM * HS;         // 64 x 84
    float* bias_s = a_s + BM * AS;         // 512

    const int tid = threadIdx.x;
    const int tx = tid & 31;       // n = tx*4 .. tx*4+3
    const int ty = tid >> 5;       // m = ty*8 .. ty*8+7
    const int b0 = blockIdx.x * BM;

    const unsigned w_u32 = (unsigned)__cvta_generic_to_shared(w_s);
    const unsigned b_off = w_u32 + tx * 16;  // byte offset of this thread's 4 n-cols

    for (int i = tid; i < NG; i += 256) bias_s[i] = g_bias[i];
    __syncthreads();

    float c_r[8][4];
    float tmp[8][4];
#pragma unroll
    for (int i = 0; i < 8; i++)
#pragma unroll
        for (int j = 0; j < 4; j++) c_r[i][j] = 0.f;

    const float* a_base = a_s + (ty * 8) * AS;
    const float* h_base = h_s + (ty * 8) * HS;

    for (int t = 0; t < TT; t++) {
        // stage w_in tile (K padded to 84 with zeros)
        for (int idx = tid; idx < BM * AS; idx += 256) {
            int m = idx / AS;
            int d = idx - m * AS;
            a_s[idx] = (d < DD) ? out_w[(((size_t)(b0 + m)) * TT + t) * DD + d] : 0.f;
        }
        __syncthreads();

#pragma unroll 1
        for (int cc = 0; cc < 4; cc++) {
            // chunk order i(0) -> g(2) -> f(1) -> o(3)
            const int q = (cc == 0) ? 0 : (cc == 1) ? 2 : (cc == 2) ? 1 : 3;

            unsigned long long acc[8][2];
#pragma unroll
            for (int i = 0; i < 8; i++) { acc[i][0] = 0ull; acc[i][1] = 0ull; }

            // stage ih weight chunk (rows 81..83 zero)
            for (int idx = tid; idx < AS * 32; idx += 256) {
                int k = idx >> 5;
                int n4 = idx & 31;
                float4 v;
                if (k < DD) v = *(const float4*)(g_Wtih + k * NG + q * HH + n4 * 4);
                else v = make_float4(0.f, 0.f, 0.f, 0.f);
                *(float4*)(w_s + k * WS + n4 * 4) = v;
            }
            __syncthreads();

            // GEMM over w_in (K = 84)
#pragma unroll 1
            for (int k = 0; k < AS; k += 4) {
                float4 a4[8];
#pragma unroll
                for (int i = 0; i < 8; i++)
                    a4[i] = *(const float4*)(a_base + i * AS + k);
#pragma unroll
                for (int kk = 0; kk < 4; kk++) {
                    unsigned long long b01, b23;
                    unsigned addr = b_off + (unsigned)((k + kk) * WS) * 4u;
                    asm volatile("ld.shared.v2.b64 {%0, %1}, [%2];"
                                 : "=l"(b01), "=l"(b23) : "r"(addr));
#pragma unroll
                    for (int i = 0; i < 8; i++) {
                        float av = (kk == 0) ? a4[i].x : (kk == 1) ? a4[i].y
                                 : (kk == 2) ? a4[i].z : a4[i].w;
                        unsigned long long ad = pack_dup(av);
                        ffma2(acc[i][0], ad, b01);
                        ffma2(acc[i][1], ad, b23);
                    }
                }
            }
            __syncthreads();

            if (t > 0) {
                // stage hh weight chunk
                for (int idx = tid; idx < HH * 32; idx += 256) {
                    int k = idx >> 5;
                    int n4 = idx & 31;
                    *(float4*)(w_s + k * WS + n4 * 4) =
                        *(const float4*)(g_Wthh + k * NG + q * HH + n4 * 4);
                }
                __syncthreads();

                // GEMM over h (K = 128)
#pragma unroll 1
                for (int k = 0; k < HH; k += 4) {
                    float4 a4[8];
#pragma unroll
                    for (int i = 0; i < 8; i++)
                        a4[i] = *(const float4*)(h_base + i * HS + k);
#pragma unroll
                    for (int kk = 0; kk < 4; kk++) {
                        unsigned long long b01, b23;
                        unsigned addr = b_off + (unsigned)((k + kk) * WS) * 4u;
                        asm volatile("ld.shared.v2.b64 {%0, %1}, [%2];"
                                     : "=l"(b01), "=l"(b23) : "r"(addr));
#pragma unroll
                        for (int i = 0; i < 8; i++) {
                            float av = (kk == 0) ? a4[i].x : (kk == 1) ? a4[i].y
                                     : (kk == 2) ? a4[i].z : a4[i].w;
                            unsigned long long ad = pack_dup(av);
                            ffma2(acc[i][0], ad, b01);
                            ffma2(acc[i][1], ad, b23);
                        }
                    }
                }
                __syncthreads();
            }

            // elementwise gate processing (thread-private (m,n) ownership)
#pragma unroll
            for (int i = 0; i < 8; i++) {
                float g[4];
                unpack2(acc[i][0], g[0], g[1]);
                unpack2(acc[i][1], g[2], g[3]);
#pragma unroll
                for (int j = 0; j < 4; j++)
                    g[j] += bias_s[q * HH + tx * 4 + j];

                if (q == 0) {
#pragma unroll
                    for (int j = 0; j < 4; j++) tmp[i][j] = sigmoidf_(g[j]);
                } else if (q == 2) {
#pragma unroll
                    for (int j = 0; j < 4; j++) tmp[i][j] *= tanhf_(g[j]);
                } else if (q == 1) {
#pragma unroll
                    for (int j = 0; j < 4; j++)
                        c_r[i][j] = sigmoidf_(g[j]) * c_r[i][j] + tmp[i][j];
                } else {
                    int m = ty * 8 + i;
                    float4 hv;
                    float h0 = sigmoidf_(g[0]) * tanhf_(c_r[i][0]);
                    float h1 = sigmoidf_(g[1]) * tanhf_(c_r[i][1]);
                    float h2 = sigmoidf_(g[2]) * tanhf_(c_r[i][2]);
                    float h3 = sigmoidf_(g[3]) * tanhf_(c_r[i][3]);
                    hv = make_float4(h0, h1, h2, h3);
                    *(float4*)(h_s + m * HS + tx * 4) = hv;
                    *(float4*)(out_enc + (((size_t)(b0 + m)) * TT + t) * HH + tx * 4) = hv;
                }
            }
            __syncthreads();
        }
    }
}

// ---------------------------------------------------------------------------
extern "C" void kernel_launch(void* const* d_in, const int* in_sizes, int n_in,
                              void* d_out, int out_size) {
    const float* x      = (const float*)d_in[0];
    const float* W_attn = (const float*)d_in[1];
    // d_in[2] = b_attn: cancels in softmax, unused
    const float* W_ih   = (const float*)d_in[3];
    const float* W_hh   = (const float*)d_in[4];
    const float* b_ih   = (const float*)d_in[5];
    const float* b_hh   = (const float*)d_in[6];

    float* out     = (float*)d_out;
    float* out_w   = out;                           // (B, 9, 81)
    float* out_enc = out + (size_t)NB * TT * DD;    // (B, 9, 128)

    prep_kernel<<<420, 256>>>(W_ih, W_hh, b_ih, b_hh);
    attn_kernel<<<NB / 8, 256>>>(x, W_attn, out_w);

    const int smem_bytes =
        (HH * WS + BM * HS + BM * AS + NG) * (int)sizeof(float);
    cudaFuncSetAttribute(rnn_kernel, cudaFuncAttributeMaxDynamicSharedMemorySize, smem_bytes);
    rnn_kernel<<<NB / BM, 256, smem_bytes>>>(out_w, out_enc);
}

// round 6
// speedup vs baseline: 4.8962x; 2.3777x over previous
#include <cuda_runtime.h>
#include <cuda_bf16.h>
#include <cstdint>
#include <math.h>

// Problem constants
#define NB 32768   // batch
#define TT 9       // time steps (T-1)
#define DD 81      // input dim
#define HH 128     // hidden
#define NG 512     // 4*HH gates

// Tiling
#define BM 128     // batch rows per CTA
#define KW 96      // w_in K padded (81 -> 96)
#define KT 224     // total A k-cols (96 w_in + 128 h)
#define AST 464    // A row stride bytes (224 bf16 used; 464 mod 128 = 80 -> 8 distinct phases)
#define BST 272    // B stage row stride bytes (128 bf16 used; 272 mod 128 = 16 -> conflict-free)

// SMEM map (bytes)
#define SM_BIAS  0          // 512 f32 = 2048
#define SM_A_HI  2048       // 128*464 = 59392
#define SM_A_LO  61440      // 59392
#define SM_B_HI  120832     // 128*272 = 34816
#define SM_B_LO  155648     // 34816
#define SM_TOTAL 190464

// device scratch: weights pre-split bf16 hi/lo, row-major [n][224]
__device__ __align__(16) __nv_bfloat16 g_Bh[NG * KT];
__device__ __align__(16) __nv_bfloat16 g_Bl[NG * KT];
__device__ float g_bias[NG];

// ---------------------------------------------------------------------------
// prep: split weights into bf16 hi/lo, layout [n][k=224] (k<81: W_ih, 81..95: 0,
// 96..223: W_hh); fuse biases.
// ---------------------------------------------------------------------------
__global__ void prep_kernel(const float* __restrict__ W_ih,
                            const float* __restrict__ W_hh,
                            const float* __restrict__ b_ih,
                            const float* __restrict__ b_hh) {
    int idx = blockIdx.x * blockDim.x + threadIdx.x;   // 512*224
    if (idx < NG * KT) {
        int n = idx / KT;
        int k = idx - n * KT;
        float w = 0.f;
        if (k < DD) w = W_ih[n * DD + k];
        else if (k >= KW) w = W_hh[n * HH + (k - KW)];
        __nv_bfloat16 hi = __float2bfloat16(w);
        __nv_bfloat16 lo = __float2bfloat16(w - __bfloat162float(hi));
        g_Bh[idx] = hi;
        g_Bl[idx] = lo;
    }
    if (idx < NG) g_bias[idx] = b_ih[idx] + b_hh[idx];
}

// ---------------------------------------------------------------------------
// attention: softmax over d of (sum_t x[b,t,d]*Wx[t]); write input_weighted.
// (softmax invariant to the per-row h/c scalar term and b_attn.)
// ---------------------------------------------------------------------------
__global__ void attn_kernel(const float* __restrict__ x,
                            const float* __restrict__ W_attn,
                            float* __restrict__ out_w) {
    int gw = (blockIdx.x * blockDim.x + threadIdx.x) >> 5;
    int lane = threadIdx.x & 31;
    if (gw >= NB) return;

    float wx[TT];
#pragma unroll
    for (int tt = 0; tt < TT; tt++) wx[tt] = W_attn[2 * HH + tt];

    const float* xb = x + (size_t)gw * TT * DD;
    float xr[3][TT];
    float pre[3];
#pragma unroll
    for (int ii = 0; ii < 3; ii++) {
        int d = lane + 32 * ii;
        float p = 0.f;
#pragma unroll
        for (int tt = 0; tt < TT; tt++) {
            float v = (d < DD) ? xb[tt * DD + d] : 0.f;
            xr[ii][tt] = v;
            p = fmaf(v, wx[tt], p);
        }
        pre[ii] = (d < DD) ? p : -3.0e38f;
    }
    float mx = fmaxf(pre[0], fmaxf(pre[1], pre[2]));
#pragma unroll
    for (int o = 16; o > 0; o >>= 1) mx = fmaxf(mx, __shfl_xor_sync(0xffffffffu, mx, o));

    float ev[3];
    float s = 0.f;
#pragma unroll
    for (int ii = 0; ii < 3; ii++) {
        int d = lane + 32 * ii;
        ev[ii] = (d < DD) ? __expf(pre[ii] - mx) : 0.f;
        s += ev[ii];
    }
#pragma unroll
    for (int o = 16; o > 0; o >>= 1) s += __shfl_xor_sync(0xffffffffu, s, o);
    float inv = 1.f / s;

    float* ob = out_w + (size_t)gw * TT * DD;
#pragma unroll
    for (int ii = 0; ii < 3; ii++) {
        int d = lane + 32 * ii;
        if (d < DD) {
            float a = ev[ii] * inv;
#pragma unroll
            for (int tt = 0; tt < TT; tt++) ob[tt * DD + d] = a * xr[ii][tt];
        }
    }
}

// ---------------------------------------------------------------------------
// helpers
// ---------------------------------------------------------------------------
__device__ __forceinline__ uint32_t smem_u32(const void* p) {
    uint32_t a;
    asm("{ .reg .u64 t; cvta.to.shared.u64 t, %1; cvt.u32.u64 %0, t; }" : "=r"(a) : "l"(p));
    return a;
}
__device__ __forceinline__ void ldsm_x4(uint32_t addr, uint32_t* r) {
    asm volatile("ldmatrix.sync.aligned.m8n8.x4.shared.b16 {%0,%1,%2,%3}, [%4];"
                 : "=r"(r[0]), "=r"(r[1]), "=r"(r[2]), "=r"(r[3]) : "r"(addr));
}
__device__ __forceinline__ void ldsm_x2(uint32_t addr, uint32_t* r) {
    asm volatile("ldmatrix.sync.aligned.m8n8.x2.shared.b16 {%0,%1}, [%2];"
                 : "=r"(r[0]), "=r"(r[1]) : "r"(addr));
}
__device__ __forceinline__ void mma16816(float* d, const uint32_t* a, const uint32_t* b) {
    asm volatile(
        "mma.sync.aligned.m16n8k16.row.col.f32.bf16.bf16.f32 "
        "{%0,%1,%2,%3}, {%4,%5,%6,%7}, {%8,%9}, {%0,%1,%2,%3};"
        : "+f"(d[0]), "+f"(d[1]), "+f"(d[2]), "+f"(d[3])
        : "r"(a[0]), "r"(a[1]), "r"(a[2]), "r"(a[3]), "r"(b[0]), "r"(b[1]));
}
__device__ __forceinline__ float sigmoidf_(float v) {
    return __fdividef(1.f, 1.f + __expf(-v));
}
__device__ __forceinline__ float tanhf_(float v) {
    return __fdividef(2.f, 1.f + __expf(-2.f * v)) - 1.f;
}
__device__ __forceinline__ void split_pack(float v0, float v1, uint32_t& h2, uint32_t& l2) {
    __nv_bfloat16 h0 = __float2bfloat16(v0);
    __nv_bfloat16 h1 = __float2bfloat16(v1);
    float r0 = v0 - __bfloat162float(h0);
    float r1 = v1 - __bfloat162float(h1);
    __nv_bfloat162 H(h0, h1);
    __nv_bfloat162 L(__float2bfloat16(r0), __float2bfloat16(r1));
    h2 = *reinterpret_cast<uint32_t*>(&H);
    l2 = *reinterpret_cast<uint32_t*>(&L);
}

// one GEMM phase: nsteps k-steps of 16, 3-term split accumulate
__device__ __forceinline__ void mma_phase(float acc[4][4][4],
                                          uint32_t aHi, uint32_t aLo,
                                          uint32_t bHi, uint32_t bLo,
                                          int nsteps) {
#pragma unroll 1
    for (int j = 0; j < nsteps; j++) {
        uint32_t bh[4][2], bl[4][2];
#pragma unroll
        for (int in = 0; in < 4; in++) {
            ldsm_x2(bHi + in * (8 * BST) + j * 32, bh[in]);
            ldsm_x2(bLo + in * (8 * BST) + j * 32, bl[in]);
        }
#pragma unroll
        for (int im = 0; im < 4; im++) {
            uint32_t ah[4], al[4];
            ldsm_x4(aHi + im * (16 * AST) + j * 32, ah);
            ldsm_x4(aLo + im * (16 * AST) + j * 32, al);
#pragma unroll
            for (int in = 0; in < 4; in++) {
                mma16816(acc[im][in], ah, bh[in]);
                mma16816(acc[im][in], ah, bl[in]);
                mma16816(acc[im][in], al, bh[in]);
            }
        }
    }
}

// ---------------------------------------------------------------------------
// recurrent HMMA kernel: 1 CTA = 128 batch rows, 256 threads (8 warps)
// ---------------------------------------------------------------------------
__global__ __launch_bounds__(256, 1)
void rnn_tc_kernel(const float* __restrict__ out_w, float* __restrict__ out_enc) {
    extern __shared__ char smem_c[];
    const uint32_t smem_base = smem_u32(smem_c);
    const int tid = threadIdx.x;
    const int wid = tid >> 5;
    const int lane = tid & 31;
    const int mw = wid & 1;        // 2 m-warps (rows 64*mw..)
    const int nw = wid >> 1;       // 4 n-warps (cols 32*nw..)
    const int b0 = blockIdx.x * BM;

    float* bias_s = (float*)(smem_c + SM_BIAS);
    for (int i = tid; i < NG; i += 256) bias_s[i] = g_bias[i];
    // zero A (hi+lo): 2*59392 B = 7424 uint4
    {
        uint4 z = make_uint4(0, 0, 0, 0);
        uint4* a4 = (uint4*)(smem_c + SM_A_HI);
        for (int i = tid; i < 7424; i += 256) a4[i] = z;
    }

    // lane-resolved ldmatrix base addresses
    const uint32_t aHiB = smem_base + SM_A_HI + (mw * 64 + (lane & 15)) * AST
                        + ((lane >> 4) & 1) * 16;
    const uint32_t aLoB = aHiB + (SM_A_LO - SM_A_HI);
    const uint32_t bHiB = smem_base + SM_B_HI + (nw * 32 + (lane & 7)) * BST
                        + ((lane >> 3) & 1) * 16;
    const uint32_t bLoB = bHiB + (SM_B_LO - SM_B_HI);

    float c_r[4][4][4];
    float tmp[4][4][4];
#pragma unroll
    for (int im = 0; im < 4; im++)
#pragma unroll
        for (int in = 0; in < 4; in++)
#pragma unroll
            for (int r = 0; r < 4; r++) c_r[im][in][r] = 0.f;

    for (int t = 0; t < TT; t++) {
        __syncthreads();   // A writes from previous t (h + w_in) vs readers
        // stage w_in tile for step t into A cols [0,82)
        for (int p = tid; p < BM * 41; p += 256) {
            int m = p / 41;
            int d = (p - m * 41) * 2;
            const float* src = out_w + (((size_t)(b0 + m)) * TT + t) * DD + d;
            float v0 = src[0];
            float v1 = (d + 1 < DD) ? src[1] : 0.f;
            uint32_t h2, l2;
            split_pack(v0, v1, h2, l2);
            *(uint32_t*)(smem_c + SM_A_HI + m * AST + d * 2) = h2;
            *(uint32_t*)(smem_c + SM_A_LO + m * AST + d * 2) = l2;
        }

#pragma unroll 1
        for (int cc = 0; cc < 4; cc++) {
            // gate order i(0) -> g(2) -> f(1) -> o(3)
            const int q = (cc == 0) ? 0 : (cc == 1) ? 2 : (cc == 2) ? 1 : 3;

            float acc[4][4][4];
#pragma unroll
            for (int im = 0; im < 4; im++)
#pragma unroll
                for (int in = 0; in < 4; in++)
#pragma unroll
                    for (int r = 0; r < 4; r++) acc[im][in][r] = 0.f;

            // ---- phase 0: w_in (k 0..95) ----
            __syncthreads();   // previous mma/readers done before Bs overwrite
            {   // stage B rows [q*128 .. q*128+127], k cols [0,96): 12 uint4/row
                for (int i = tid; i < BM * 12; i += 256) {
                    int n = i / 12;
                    int ck = i - n * 12;
                    size_t g = (size_t)(q * BM + n) * KT;
                    *((uint4*)(smem_c + SM_B_HI + n * BST) + ck) =
                        *((const uint4*)(g_Bh + g) + ck);
                    *((uint4*)(smem_c + SM_B_LO + n * BST) + ck) =
                        *((const uint4*)(g_Bl + g) + ck);
                }
            }
            __syncthreads();
            mma_phase(acc, aHiB, aLoB, bHiB, bLoB, KW / 16);

            // ---- phase 1: h (k 96..223), skip at t=0 (h == 0) ----
            if (t > 0) {
                __syncthreads();
                for (int i = tid; i < BM * 16; i += 256) {
                    int n = i / 16;
                    int ck = i - n * 16;
                    size_t g = (size_t)(q * BM + n) * KT + KW;
                    *((uint4*)(smem_c + SM_B_HI + n * BST) + ck) =
                        *((const uint4*)(g_Bh + g) + ck);
                    *((uint4*)(smem_c + SM_B_LO + n * BST) + ck) =
                        *((const uint4*)(g_Bl + g) + ck);
                }
                __syncthreads();
                mma_phase(acc, aHiB + KW * 2, aLoB + KW * 2, bHiB, bLoB, HH / 16);
            }

            if (q == 3) __syncthreads();  // A-h writers below vs ldmatrix readers

            // ---- elementwise on this gate chunk ----
#pragma unroll
            for (int im = 0; im < 4; im++) {
#pragma unroll
                for (int in = 0; in < 4; in++) {
#pragma unroll
                    for (int rh = 0; rh < 2; rh++) {
                        const int m = mw * 64 + im * 16 + (lane >> 2) + rh * 8;
                        const int n0 = nw * 32 + in * 8 + (lane & 3) * 2;
                        float g0 = acc[im][in][rh * 2]     + bias_s[q * HH + n0];
                        float g1 = acc[im][in][rh * 2 + 1] + bias_s[q * HH + n0 + 1];
                        if (q == 0) {
                            tmp[im][in][rh * 2]     = sigmoidf_(g0);
                            tmp[im][in][rh * 2 + 1] = sigmoidf_(g1);
                        } else if (q == 2) {
                            tmp[im][in][rh * 2]     *= tanhf_(g0);
                            tmp[im][in][rh * 2 + 1] *= tanhf_(g1);
                        } else if (q == 1) {
                            c_r[im][in][rh * 2] =
                                sigmoidf_(g0) * c_r[im][in][rh * 2] + tmp[im][in][rh * 2];
                            c_r[im][in][rh * 2 + 1] =
                                sigmoidf_(g1) * c_r[im][in][rh * 2 + 1] + tmp[im][in][rh * 2 + 1];
                        } else {
                            float h0 = sigmoidf_(g0) * tanhf_(c_r[im][in][rh * 2]);
                            float h1 = sigmoidf_(g1) * tanhf_(c_r[im][in][rh * 2 + 1]);
                            // write out_enc
                            *(float2*)(out_enc + (((size_t)(b0 + m)) * TT + t) * HH + n0) =
                                make_float2(h0, h1);
                            // write h (bf16 hi/lo) into A cols 96+n
                            if (t + 1 < TT) {
                                uint32_t h2, l2;
                                split_pack(h0, h1, h2, l2);
                                *(uint32_t*)(smem_c + SM_A_HI + m * AST + (KW + n0) * 2) = h2;
                                *(uint32_t*)(smem_c + SM_A_LO + m * AST + (KW + n0) * 2) = l2;
                            }
                        }
                    }
                }
            }
        }
    }
}

// ---------------------------------------------------------------------------
extern "C" void kernel_launch(void* const* d_in, const int* in_sizes, int n_in,
                              void* d_out, int out_size) {
    const float* x      = (const float*)d_in[0];
    const float* W_attn = (const float*)d_in[1];
    // d_in[2] = b_attn: cancels in softmax, unused
    const float* W_ih   = (const float*)d_in[3];
    const float* W_hh   = (const float*)d_in[4];
    const float* b_ih   = (const float*)d_in[5];
    const float* b_hh   = (const float*)d_in[6];

    float* out     = (float*)d_out;
    float* out_w   = out;                           // (B, 9, 81)
    float* out_enc = out + (size_t)NB * TT * DD;    // (B, 9, 128)

    prep_kernel<<<448, 256>>>(W_ih, W_hh, b_ih, b_hh);
    attn_kernel<<<NB / 8, 256>>>(x, W_attn, out_w);

    cudaFuncSetAttribute(rnn_tc_kernel, cudaFuncAttributeMaxDynamicSharedMemorySize, SM_TOTAL);
    rnn_tc_kernel<<<NB / BM, 256, SM_TOTAL>>>(out_w, out_enc);
}